// round 7
// baseline (speedup 1.0000x reference)
#include <cuda_runtime.h>
#include <math.h>

#define B_ 128
#define L_ 128
#define H_ 1024
#define A_ 256
#define M_ 151
#define TOUT_ 24

__device__ float g_h1[B_ * L_ * 34];
__device__ float g_h2[B_ * L_ * 32];
__device__ float g_lstm_in[B_ * L_ * 18];
__device__ float g_buf[B_ * M_ * H_];
__device__ float g_hbuf[2][B_ * H_];
__device__ float g_c[B_ * H_];
__device__ float g_kp[B_ * M_ * A_];
__device__ float g_qp[B_ * 2 * A_];
__device__ float g_wts[B_ * 2 * M_];
__device__ float g_ctx[B_ * 2 * H_];

__device__ __forceinline__ float sigm(float x) { return 1.0f / (1.0f + __expf(-x)); }
__device__ __forceinline__ float ftanh(float x) {
    float e = __expf(-2.0f * fabsf(x));
    float t = (1.0f - e) * __frcp_rn(1.0f + e);
    return copysignf(t, x);
}

__global__ void zero_k() {
    int i = blockIdx.x * blockDim.x + threadIdx.x;
    if (i < B_ * H_) { g_hbuf[0][i] = 0.0f; g_c[i] = 0.0f; }
}

// conv over channel dim (L=128 channels), width = feature axis
template <int WIN, int WOUT, int ISTRIDE, int ACT, int SRC>
__global__ void __launch_bounds__(128) conv_k(const float* __restrict__ xin,
                                              const float* __restrict__ W,
                                              const float* __restrict__ bias) {
    int b = blockIdx.x, o = threadIdx.x;
    const float* in = (SRC == 0) ? xin : g_h1;
    float* out = (SRC == 0) ? g_h1 : g_h2;
    __shared__ float sIn[16 * WIN];
    float acc[WOUT];
#pragma unroll
    for (int w = 0; w < WOUT; w++) acc[w] = 0.0f;
    for (int i0 = 0; i0 < 128; i0 += 16) {
        __syncthreads();
        for (int e = o; e < 16 * WIN; e += 128) {
            int ii = e / WIN, w = e - ii * WIN;
            sIn[e] = in[(b * 128 + i0 + ii) * ISTRIDE + w];
        }
        __syncthreads();
        float wr[48];
        const float4* wp = reinterpret_cast<const float4*>(&W[(o * 128 + i0) * 3]);
#pragma unroll
        for (int q = 0; q < 12; q++) {
            float4 v = wp[q];
            wr[q * 4] = v.x; wr[q * 4 + 1] = v.y; wr[q * 4 + 2] = v.z; wr[q * 4 + 3] = v.w;
        }
#pragma unroll
        for (int ii = 0; ii < 16; ii++)
#pragma unroll
            for (int w = 0; w < WOUT; w++)
                acc[w] = fmaf(wr[ii * 3], sIn[ii * WIN + w],
                         fmaf(wr[ii * 3 + 1], sIn[ii * WIN + w + 1],
                         fmaf(wr[ii * 3 + 2], sIn[ii * WIN + w + 2], acc[w])));
    }
    float bv = bias[o];
#pragma unroll
    for (int w = 0; w < WOUT; w++) {
        float v = acc[w] + bv;
        if (ACT == 0) v = (v > 20.0f) ? v : log1pf(__expf(v));
        else          v = fmaxf(v, 0.0f);
        out[(b * 128 + o) * WOUT + w] = v;
    }
}

__global__ void __launch_bounds__(256) lin3_k(const float* __restrict__ x,
                                              const float* __restrict__ Wl,
                                              const float* __restrict__ bl) {
    int b = blockIdx.x;
    __shared__ float s2[128 * 32];
    for (int e = threadIdx.x; e < 128 * 32; e += 256) s2[e] = g_h2[b * 128 * 32 + e];
    __syncthreads();
    for (int idx = threadIdx.x; idx < 128 * 18; idx += 256) {
        int l = idx / 18, j = idx - l * 18;
        float v;
        if (j < 6) {
            float a = bl[j];
#pragma unroll
            for (int f = 0; f < 32; f++) a = fmaf(s2[l * 32 + f], Wl[j * 32 + f], a);
            v = a;
        } else v = x[(b * 128 + l) * 48 + 36 + (j - 6)];
        g_lstm_in[(b * 128 + l) * 18 + j] = v;
    }
}

// fused LSTM step GEMM + pointwise. Tile 32b x 128n (4 gates x 32 j). grid (32,4).
__global__ void __launch_bounds__(256) enc_step_k(const float* __restrict__ Wih,
                                                  const float* __restrict__ Whh,
                                                  const float* __restrict__ bias,
                                                  int t, int cur) {
    const int j0 = blockIdx.x * 32, b0 = blockIdx.y * 32;
    const float* __restrict__ hprev = g_hbuf[cur];
    float* __restrict__ hnext = g_hbuf[cur ^ 1];
    __shared__ float sA[32 * 36];
    __shared__ float sB[32 * 132];
    __shared__ float sG[32 * 128];
    int tid = threadIdx.x, tx = tid & 31, ty = tid >> 5;
    float acc[4][4];
#pragma unroll
    for (int i = 0; i < 4; i++)
#pragma unroll
        for (int j = 0; j < 4; j++) acc[i][j] = 0.0f;
    int nb = tx * 4;
    int row0 = ((nb >> 5) << 10) + j0 + (nb & 31);
#pragma unroll 1
    for (int e = 0; e < 18; e++) {
        float wv[4];
#pragma unroll
        for (int jn = 0; jn < 4; jn++) wv[jn] = Wih[(row0 + jn) * 18 + e];
#pragma unroll
        for (int ib = 0; ib < 4; ib++) {
            float av = g_lstm_in[((b0 + ty * 4 + ib) * L_ + t) * 18 + e];
#pragma unroll
            for (int jn = 0; jn < 4; jn++) acc[ib][jn] = fmaf(av, wv[jn], acc[ib][jn]);
        }
    }
    for (int k0 = 0; k0 < H_; k0 += 32) {
        __syncthreads();
#pragma unroll
        for (int r = 0; r < 4; r++) {
            int e = r * 256 + tid, kk = e & 31, i = e >> 5;
            sA[kk * 36 + i] = hprev[(b0 + i) * H_ + k0 + kk];
        }
#pragma unroll
        for (int r = 0; r < 16; r++) {
            int e = r * 256 + tid, kk = e & 31, n = e >> 5;
            int row = ((n >> 5) << 10) + j0 + (n & 31);
            sB[kk * 132 + n] = Whh[row * H_ + k0 + kk];
        }
        __syncthreads();
#pragma unroll
        for (int kk = 0; kk < 32; kk++) {
            float4 av = *(const float4*)&sA[kk * 36 + ty * 4];
            float4 bv = *(const float4*)&sB[kk * 132 + tx * 4];
            float a4[4] = {av.x, av.y, av.z, av.w};
            float b4[4] = {bv.x, bv.y, bv.z, bv.w};
#pragma unroll
            for (int i = 0; i < 4; i++)
#pragma unroll
                for (int j = 0; j < 4; j++) acc[i][j] = fmaf(a4[i], b4[j], acc[i][j]);
        }
    }
    __syncthreads();
#pragma unroll
    for (int ib = 0; ib < 4; ib++)
#pragma unroll
        for (int jn = 0; jn < 4; jn++)
            sG[(ty * 4 + ib) * 128 + nb + jn] = acc[ib][jn] + bias[row0 + jn];
    __syncthreads();
#pragma unroll
    for (int r = 0; r < 4; r++) {
        int p = r * 256 + tid, bl = p >> 5, jl = p & 31;
        float gi = sG[bl * 128 + jl], gf = sG[bl * 128 + 32 + jl];
        float gg = sG[bl * 128 + 64 + jl], go = sG[bl * 128 + 96 + jl];
        int b = b0 + bl, j = j0 + jl;
        float cn = sigm(gf) * g_c[b * H_ + j] + sigm(gi) * tanhf(gg);
        float hn = sigm(go) * tanhf(cn);
        g_c[b * H_ + j] = cn;
        hnext[b * H_ + j] = hn;
        g_buf[(b * M_ + t) * H_ + j] = hn;
    }
}

// kp init for the 127 static rows per batch. grid (4, 254).
__global__ void __launch_bounds__(256) kpinit_k(const float* __restrict__ Wk) {
    int n0 = blockIdx.x * 64, r0 = blockIdx.y * 64;
    __shared__ float sA[16 * 68];
    __shared__ float sW[16 * 68];
    int tid = threadIdx.x, tx = tid & 15, ty = tid >> 4;
    float acc[4][4];
#pragma unroll
    for (int i = 0; i < 4; i++)
#pragma unroll
        for (int j = 0; j < 4; j++) acc[i][j] = 0.0f;
    for (int k0 = 0; k0 < H_; k0 += 16) {
        __syncthreads();
#pragma unroll
        for (int r = 0; r < 4; r++) {
            int e = r * 256 + tid, kk = e & 15, rr = e >> 4;
            int row = r0 + rr, b = row / 127, m = row - b * 127;
            sA[kk * 68 + rr] = g_buf[(b * M_ + m) * H_ + k0 + kk];
        }
#pragma unroll
        for (int r = 0; r < 4; r++) {
            int e = r * 256 + tid, kk = e & 15, nn = e >> 4;
            sW[kk * 68 + nn] = Wk[(n0 + nn) * H_ + k0 + kk];
        }
        __syncthreads();
#pragma unroll
        for (int kk = 0; kk < 16; kk++) {
            float4 av = *(const float4*)&sA[kk * 68 + ty * 4];
            float4 bv = *(const float4*)&sW[kk * 68 + tx * 4];
            float a4[4] = {av.x, av.y, av.z, av.w};
            float b4[4] = {bv.x, bv.y, bv.z, bv.w};
#pragma unroll
            for (int i = 0; i < 4; i++)
#pragma unroll
                for (int j = 0; j < 4; j++) acc[i][j] = fmaf(a4[i], b4[j], acc[i][j]);
        }
    }
#pragma unroll
    for (int i = 0; i < 4; i++) {
        int row = r0 + ty * 4 + i, b = row / 127, m = row - b * 127;
#pragma unroll
        for (int j = 0; j < 4; j++)
            g_kp[(b * M_ + m) * A_ + n0 + tx * 4 + j] = acc[i][j];
    }
}

__global__ void bufrow_k(int cur, int t) {
    int b = blockIdx.x;
    const float* h = &g_hbuf[cur][b * H_];
    float* dst = &g_buf[(b * M_ + 127 + t) * H_];
    for (int k = threadIdx.x; k < H_; k += blockDim.x) dst[k] = h[k];
}

// kp row 127+t = s @ Wk^T. grid (8, 16): 32 a per block-x, 8 b per block-y.
__global__ void __launch_bounds__(256) kprow_k(const float* __restrict__ Wk, int cur, int t) {
    int a0 = blockIdx.x * 32, b0 = blockIdx.y * 8;
    const float* __restrict__ h = g_hbuf[cur];
    __shared__ float sW[32 * 33];
    __shared__ float sH[32 * 8];
    int tid = threadIdx.x, lane = tid & 31, wid = tid >> 5;
    float acc = 0.0f;
    for (int k0 = 0; k0 < H_; k0 += 32) {
        __syncthreads();
#pragma unroll
        for (int r = 0; r < 4; r++) {
            int e = r * 256 + tid, kk = e & 31, a = e >> 5;
            sW[kk * 33 + a] = Wk[(a0 + a) * H_ + k0 + kk];
        }
        sH[(tid & 31) * 8 + (tid >> 5)] = h[(b0 + (tid >> 5)) * H_ + k0 + (tid & 31)];
        __syncthreads();
#pragma unroll
        for (int kk = 0; kk < 32; kk++) acc = fmaf(sH[kk * 8 + wid], sW[kk * 33 + lane], acc);
    }
    g_kp[((b0 + wid) * M_ + 127 + t) * A_ + a0 + lane] = acc;
}

__global__ void __launch_bounds__(256) qp_k(const float* __restrict__ Wq, int cur) {
    int a0 = blockIdx.x * 32, b0 = blockIdx.y * 8;
    const float* __restrict__ h = g_hbuf[cur];
    __shared__ float sW[32 * 33];
    __shared__ float sH[32 * 8];
    __shared__ float sC[32 * 8];
    int tid = threadIdx.x, lane = tid & 31, wid = tid >> 5;
    float a0c = 0.0f, a1c = 0.0f;
    for (int k0 = 0; k0 < H_; k0 += 32) {
        __syncthreads();
#pragma unroll
        for (int r = 0; r < 4; r++) {
            int e = r * 256 + tid, kk = e & 31, a = e >> 5;
            sW[kk * 33 + a] = Wq[(a0 + a) * H_ + k0 + kk];
        }
        {
            int kk = tid & 31, bb = tid >> 5;
            sH[kk * 8 + bb] = h[(b0 + bb) * H_ + k0 + kk];
            sC[kk * 8 + bb] = g_c[(b0 + bb) * H_ + k0 + kk];
        }
        __syncthreads();
#pragma unroll
        for (int kk = 0; kk < 32; kk++) {
            float w = sW[kk * 33 + lane];
            a0c = fmaf(sH[kk * 8 + wid], w, a0c);
            a1c = fmaf(sC[kk * 8 + wid], w, a1c);
        }
    }
    int b = b0 + wid;
    g_qp[b * 512 + a0 + lane] = a0c;
    g_qp[b * 512 + 256 + a0 + lane] = a1c;
}

// scores + 2-way softmax. grid (19, B), one warp per m.
__global__ void __launch_bounds__(256) attn_scores_k(const float* __restrict__ Wv, int t) {
    int b = blockIdx.y;
    int m = blockIdx.x * 8 + (threadIdx.x >> 5);
    int lane = threadIdx.x & 31, Mt = 128 + t;
    __shared__ float sqp[512];
    __shared__ float sv[256];
    for (int e = threadIdx.x; e < 512; e += 256) sqp[e] = g_qp[b * 512 + e];
    if (threadIdx.x < 256) sv[threadIdx.x] = Wv[threadIdx.x];
    __syncthreads();
    if (m < Mt) {
        const float* kpm = &g_kp[(b * M_ + m) * A_];
        float s0 = 0.0f, s1 = 0.0f;
#pragma unroll
        for (int aa = 0; aa < 8; aa++) {
            int a = lane + aa * 32;
            float kv = kpm[a], v = sv[a];
            s0 = fmaf(ftanh(sqp[a] + kv), v, s0);
            s1 = fmaf(ftanh(sqp[256 + a] + kv), v, s1);
        }
#pragma unroll
        for (int off = 16; off > 0; off >>= 1) {
            s0 += __shfl_down_sync(0xffffffffu, s0, off);
            s1 += __shfl_down_sync(0xffffffffu, s1, off);
        }
        if (lane == 0) {
            float mx = fmaxf(s0, s1);
            float e0 = __expf(s0 - mx), e1 = __expf(s1 - mx);
            float inv = 1.0f / (e0 + e1);
            g_wts[b * 2 * M_ + m] = e0 * inv;
            g_wts[b * 2 * M_ + M_ + m] = e1 * inv;
        }
    }
}

// ctx[b][n*H+h] = sum_m w[b][n][m]*buf[b][m][h]. grid (4, B).
__global__ void __launch_bounds__(256) ctx_k(int t) {
    int b = blockIdx.y;
    int hh = blockIdx.x * 256 + threadIdx.x;
    int Mt = 128 + t;
    __shared__ float w0[M_], w1[M_];
    for (int e = threadIdx.x; e < Mt; e += 256) {
        w0[e] = g_wts[b * 2 * M_ + e];
        w1[e] = g_wts[b * 2 * M_ + M_ + e];
    }
    __syncthreads();
    float a0 = 0.0f, a1 = 0.0f;
    const float* bp = &g_buf[b * M_ * H_ + hh];
    for (int m = 0; m < Mt; m++) {
        float v = bp[m * H_];
        a0 = fmaf(w0[m], v, a0);
        a1 = fmaf(w1[m], v, a1);
    }
    g_ctx[b * 2048 + hh] = a0;
    g_ctx[b * 2048 + 1024 + hh] = a1;
}

__global__ void __launch_bounds__(256) dec_step_k(const float* __restrict__ Wih,
                                                  const float* __restrict__ Whh,
                                                  const float* __restrict__ bias,
                                                  int cur) {
    const int j0 = blockIdx.x * 32, b0 = blockIdx.y * 32;
    const float* __restrict__ hprev = g_hbuf[cur];
    float* __restrict__ hnext = g_hbuf[cur ^ 1];
    __shared__ float sA[32 * 36];
    __shared__ float sB[32 * 132];
    __shared__ float sG[32 * 128];
    int tid = threadIdx.x, tx = tid & 31, ty = tid >> 5;
    float acc[4][4];
#pragma unroll
    for (int i = 0; i < 4; i++)
#pragma unroll
        for (int j = 0; j < 4; j++) acc[i][j] = 0.0f;
    int nb = tx * 4;
    int row0 = ((nb >> 5) << 10) + j0 + (nb & 31);
    // K = 3072 : first 2048 from ctx/Wih, then 1024 from h/Whh
    for (int kseg = 0; kseg < 3072; kseg += 32) {
        int isH = (kseg >= 2048);
        int k0 = isH ? (kseg - 2048) : kseg;
        __syncthreads();
#pragma unroll
        for (int r = 0; r < 4; r++) {
            int e = r * 256 + tid, kk = e & 31, i = e >> 5;
            sA[kk * 36 + i] = isH ? hprev[(b0 + i) * H_ + k0 + kk]
                                  : g_ctx[(b0 + i) * 2048 + k0 + kk];
        }
#pragma unroll
        for (int r = 0; r < 16; r++) {
            int e = r * 256 + tid, kk = e & 31, n = e >> 5;
            int row = ((n >> 5) << 10) + j0 + (n & 31);
            sB[kk * 132 + n] = isH ? Whh[row * H_ + k0 + kk]
                                   : Wih[row * 2048 + k0 + kk];
        }
        __syncthreads();
#pragma unroll
        for (int kk = 0; kk < 32; kk++) {
            float4 av = *(const float4*)&sA[kk * 36 + ty * 4];
            float4 bv = *(const float4*)&sB[kk * 132 + tx * 4];
            float a4[4] = {av.x, av.y, av.z, av.w};
            float b4[4] = {bv.x, bv.y, bv.z, bv.w};
#pragma unroll
            for (int i = 0; i < 4; i++)
#pragma unroll
                for (int j = 0; j < 4; j++) acc[i][j] = fmaf(a4[i], b4[j], acc[i][j]);
        }
    }
    __syncthreads();
#pragma unroll
    for (int ib = 0; ib < 4; ib++)
#pragma unroll
        for (int jn = 0; jn < 4; jn++)
            sG[(ty * 4 + ib) * 128 + nb + jn] = acc[ib][jn] + bias[row0 + jn];
    __syncthreads();
#pragma unroll
    for (int r = 0; r < 4; r++) {
        int p = r * 256 + tid, bl = p >> 5, jl = p & 31;
        float gi = sG[bl * 128 + jl], gf = sG[bl * 128 + 32 + jl];
        float gg = sG[bl * 128 + 64 + jl], go = sG[bl * 128 + 96 + jl];
        int b = b0 + bl, j = j0 + jl;
        float cn = sigm(gf) * g_c[b * H_ + j] + sigm(gi) * tanhf(gg);
        float hn = sigm(go) * tanhf(cn);
        g_c[b * H_ + j] = cn;
        hnext[b * H_ + j] = hn;
    }
}

__global__ void __launch_bounds__(256) out_k(const float* __restrict__ ow,
                                             const float* __restrict__ ob,
                                             int idx, int t, float* __restrict__ out) {
    int b = blockIdx.x;
    const float* h = g_hbuf[idx];
    float s = 0.0f;
    for (int k = threadIdx.x; k < H_; k += 256) s = fmaf(h[b * H_ + k], ow[k], s);
    __shared__ float red[256];
    red[threadIdx.x] = s;
    __syncthreads();
    for (int off = 128; off > 0; off >>= 1) {
        if (threadIdx.x < off) red[threadIdx.x] += red[threadIdx.x + off];
        __syncthreads();
    }
    if (threadIdx.x == 0) out[b * TOUT_ + t] = red[0] + ob[0];
}

extern "C" void kernel_launch(void* const* d_in, const int* in_sizes, int n_in,
                              void* d_out, int out_size) {
    const float* x    = (const float*)d_in[0];
    const float* c1w  = (const float*)d_in[1];
    const float* c1b  = (const float*)d_in[2];
    const float* c2w  = (const float*)d_in[3];
    const float* c2b  = (const float*)d_in[4];
    const float* l3w  = (const float*)d_in[5];
    const float* l3b  = (const float*)d_in[6];
    const float* eWih = (const float*)d_in[7];
    const float* eWhh = (const float*)d_in[8];
    const float* eb   = (const float*)d_in[9];
    const float* Wq   = (const float*)d_in[10];
    const float* Wk   = (const float*)d_in[11];
    const float* Wv   = (const float*)d_in[12];
    const float* dWih = (const float*)d_in[13];
    const float* dWhh = (const float*)d_in[14];
    const float* db   = (const float*)d_in[15];
    const float* ow   = (const float*)d_in[16];
    const float* ob   = (const float*)d_in[17];
    float* out = (float*)d_out;

    zero_k<<<(B_ * H_ + 255) / 256, 256>>>();
    conv_k<36, 34, 48, 0, 0><<<B_, 128>>>(x, c1w, c1b);   // softplus
    conv_k<34, 32, 34, 1, 1><<<B_, 128>>>(x, c2w, c2b);   // relu
    lin3_k<<<B_, 256>>>(x, l3w, l3b);

    int cur = 0;
    for (int t = 0; t < L_; t++) {
        enc_step_k<<<dim3(32, 4), 256>>>(eWih, eWhh, eb, t, cur);
        cur ^= 1;
    }
    kpinit_k<<<dim3(4, 254), 256>>>(Wk);
    for (int t = 0; t < TOUT_; t++) {
        bufrow_k<<<B_, 256>>>(cur, t);
        kprow_k<<<dim3(8, 16), 256>>>(Wk, cur, t);
        qp_k<<<dim3(8, 16), 256>>>(Wq, cur);
        attn_scores_k<<<dim3(19, B_), 256>>>(Wv, t);
        ctx_k<<<dim3(4, B_), 256>>>(t);
        dec_step_k<<<dim3(32, 4), 256>>>(dWih, dWhh, db, cur);
        out_k<<<B_, 256>>>(ow, ob, cur ^ 1, t, out);
        cur ^= 1;
    }
}

// round 10
// speedup vs baseline: 1.5458x; 1.5458x over previous
#include <cuda_runtime.h>
#include <math.h>

#define B_ 128
#define L_ 128
#define H_ 1024
#define A_ 256
#define M_ 151
#define TOUT_ 24
#define KS_ 8

typedef unsigned long long u64;

__device__ float g_h1[B_ * L_ * 34];
__device__ float g_h2[B_ * L_ * 32];
__device__ float g_lstm_in[B_ * L_ * 18];
__device__ float g_buf[B_ * M_ * H_];
__device__ float g_hbuf[2][B_ * H_];
__device__ float g_c[B_ * H_];
__device__ float g_kp[B_ * M_ * A_];
__device__ float g_qp[B_ * 2 * A_];
__device__ float g_wts[B_ * 2 * M_];
__device__ float g_ctx[B_ * 2 * H_];
__device__ float g_gpart[KS_ * B_ * 4096];   // split-K partial gates

__device__ __forceinline__ float sigm(float x) { return 1.0f / (1.0f + __expf(-x)); }
__device__ __forceinline__ float ftanh(float x) {
    float e = __expf(-2.0f * fabsf(x));
    float t = (1.0f - e) * __frcp_rn(1.0f + e);
    return copysignf(t, x);
}

// ---- packed fp32x2 FMA (Blackwell FFMA2; ptxas never auto-generates) ----
__device__ __forceinline__ u64 pack2(float lo, float hi) {
    u64 r; asm("mov.b64 %0, {%1, %2};" : "=l"(r) : "f"(lo), "f"(hi)); return r;
}
__device__ __forceinline__ void fma2(u64& d, u64 a, u64 b) {
    asm("fma.rn.f32x2 %0, %1, %2, %0;" : "+l"(d) : "l"(a), "l"(b));
}
__device__ __forceinline__ float2 unpack2(u64 v) {
    float2 f; asm("mov.b64 {%0, %1}, %2;" : "=f"(f.x), "=f"(f.y) : "l"(v)); return f;
}

__global__ void zero_k() {
    int i = blockIdx.x * blockDim.x + threadIdx.x;
    if (i < B_ * H_) { g_hbuf[0][i] = 0.0f; g_c[i] = 0.0f; }
}

// ---------------- conv frontend ----------------
template <int WIN, int WOUT, int ISTRIDE, int ACT, int SRC>
__global__ void __launch_bounds__(128) conv_k(const float* __restrict__ xin,
                                              const float* __restrict__ W,
                                              const float* __restrict__ bias) {
    int b = blockIdx.x, o = threadIdx.x;
    const float* in = (SRC == 0) ? xin : g_h1;
    float* out = (SRC == 0) ? g_h1 : g_h2;
    __shared__ float sIn[16 * WIN];
    float acc[WOUT];
#pragma unroll
    for (int w = 0; w < WOUT; w++) acc[w] = 0.0f;
    for (int i0 = 0; i0 < 128; i0 += 16) {
        __syncthreads();
        for (int e = o; e < 16 * WIN; e += 128) {
            int ii = e / WIN, w = e - ii * WIN;
            sIn[e] = in[(b * 128 + i0 + ii) * ISTRIDE + w];
        }
        __syncthreads();
        float wr[48];
        const float4* wp = reinterpret_cast<const float4*>(&W[(o * 128 + i0) * 3]);
#pragma unroll
        for (int q = 0; q < 12; q++) {
            float4 v = wp[q];
            wr[q * 4] = v.x; wr[q * 4 + 1] = v.y; wr[q * 4 + 2] = v.z; wr[q * 4 + 3] = v.w;
        }
#pragma unroll
        for (int ii = 0; ii < 16; ii++)
#pragma unroll
            for (int w = 0; w < WOUT; w++)
                acc[w] = fmaf(wr[ii * 3], sIn[ii * WIN + w],
                         fmaf(wr[ii * 3 + 1], sIn[ii * WIN + w + 1],
                         fmaf(wr[ii * 3 + 2], sIn[ii * WIN + w + 2], acc[w])));
    }
    float bv = bias[o];
#pragma unroll
    for (int w = 0; w < WOUT; w++) {
        float v = acc[w] + bv;
        if (ACT == 0) v = (v > 20.0f) ? v : log1pf(__expf(v));
        else          v = fmaxf(v, 0.0f);
        out[(b * 128 + o) * WOUT + w] = v;
    }
}

__global__ void __launch_bounds__(256) lin3_k(const float* __restrict__ x,
                                              const float* __restrict__ Wl,
                                              const float* __restrict__ bl) {
    int b = blockIdx.x;
    __shared__ float s2[128 * 32];
    for (int e = threadIdx.x; e < 128 * 32; e += 256) s2[e] = g_h2[b * 128 * 32 + e];
    __syncthreads();
    for (int idx = threadIdx.x; idx < 128 * 18; idx += 256) {
        int l = idx / 18, j = idx - l * 18;
        float v;
        if (j < 6) {
            float a = bl[j];
#pragma unroll
            for (int f = 0; f < 32; f++) a = fmaf(s2[l * 32 + f], Wl[j * 32 + f], a);
            v = a;
        } else v = x[(b * 128 + l) * 48 + 36 + (j - 6)];
        g_lstm_in[(b * 128 + l) * 18 + j] = v;
    }
}

// ---------------- split-K gate GEMM with FFMA2 ----------------
// gpart[ks][b][n] = sum_{k in chunk ks} A[b][k] * W[n][k]
// A(k) = k<len0 ? A0 : A1 ; W(n,k) = k<len0 ? W0 : W1.
// Tile: 128b x 128n, micro 8x8, 256 threads. grid (32 n-tiles, KS_).
__global__ void __launch_bounds__(256, 2) gates_k(
    int asel, int cur,
    const float* __restrict__ W0, int ldw0,
    const float* __restrict__ W1, int ldw1,
    int len0, int kChunk)
{
    const float *A0, *A1;
    int lda0, lda1;
    if (asel == 0) { A0 = g_hbuf[cur]; lda0 = H_; A1 = A0; lda1 = H_; }
    else           { A0 = g_ctx;       lda0 = 2 * H_; A1 = g_hbuf[cur]; lda1 = H_; }

    const int j0 = blockIdx.x * 32;
    const int ks = blockIdx.y;
    const int kbase = ks * kChunk;
    __shared__ float sA[16 * 132];
    __shared__ float sB[16 * 132];
    int tid = threadIdx.x, tx = tid & 15, ty = tid >> 4;

    u64 acc[8][4];
#pragma unroll
    for (int i = 0; i < 8; i++)
#pragma unroll
        for (int jp = 0; jp < 4; jp++) acc[i][jp] = 0ull;

    for (int kb = 0; kb < kChunk; kb += 16) {
        __syncthreads();
#pragma unroll
        for (int r = 0; r < 8; r++) {
            int e = r * 256 + tid;
            int kk = e & 15, bb = e >> 4;
            int kg = kbase + kb + kk;
            float v = (kg < len0) ? A0[bb * lda0 + kg] : A1[bb * lda1 + kg - len0];
            sA[kk * 132 + bb] = v;
        }
#pragma unroll
        for (int r = 0; r < 8; r++) {
            int e = r * 256 + tid;
            int kk = e & 15, n = e >> 4;
            int row = ((n >> 5) << 10) + j0 + (n & 31);
            int kg = kbase + kb + kk;
            float v = (kg < len0) ? W0[row * ldw0 + kg] : W1[row * ldw1 + kg - len0];
            sB[kk * 132 + n] = v;
        }
        __syncthreads();
#pragma unroll
        for (int kk = 0; kk < 16; kk++) {
            float4 b0 = *(const float4*)&sB[kk * 132 + tx * 8];
            float4 b1 = *(const float4*)&sB[kk * 132 + tx * 8 + 4];
            u64 bp[4];
            bp[0] = pack2(b0.x, b0.y); bp[1] = pack2(b0.z, b0.w);
            bp[2] = pack2(b1.x, b1.y); bp[3] = pack2(b1.z, b1.w);
            float4 a0v = *(const float4*)&sA[kk * 132 + ty * 8];
            float4 a1v = *(const float4*)&sA[kk * 132 + ty * 8 + 4];
            float aa[8] = {a0v.x, a0v.y, a0v.z, a0v.w, a1v.x, a1v.y, a1v.z, a1v.w};
#pragma unroll
            for (int i = 0; i < 8; i++) {
                u64 ap = pack2(aa[i], aa[i]);
#pragma unroll
                for (int jp = 0; jp < 4; jp++) fma2(acc[i][jp], ap, bp[jp]);
            }
        }
    }
    // store: 8 consecutive n within one gate-group (tx*8), 8 b rows
    int nl = tx * 8;
    int row = ((nl >> 5) << 10) + j0 + (nl & 31);
#pragma unroll
    for (int i = 0; i < 8; i++) {
        int b = ty * 8 + i;
        float* dst = &g_gpart[((size_t)ks * B_ + b) * 4096 + row];
        float2 p0 = unpack2(acc[i][0]), p1 = unpack2(acc[i][1]);
        float2 p2 = unpack2(acc[i][2]), p3 = unpack2(acc[i][3]);
        float4 v0 = make_float4(p0.x, p0.y, p1.x, p1.y);
        float4 v1 = make_float4(p2.x, p2.y, p3.x, p3.y);
        *(float4*)dst = v0;
        *(float4*)(dst + 4) = v1;
    }
}

// ---------------- reduce partials + (optional input GEMM) + LSTM pointwise ----
__global__ void __launch_bounds__(256) lstm_pw_k(
    const float* __restrict__ Wih,   // [4096][18] (enc only)
    const float* __restrict__ bias,
    int t, int cur, int hasX, int writeBufRow)
{
    int idx = blockIdx.x * 256 + threadIdx.x;   // (b, j)
    int b = idx >> 10, j = idx & 1023;
    float g[4];
#pragma unroll
    for (int gi = 0; gi < 4; gi++) {
        int n = gi * 1024 + j;
        float s = bias[n];
#pragma unroll
        for (int ks = 0; ks < KS_; ks++)
            s += g_gpart[((size_t)ks * B_ + b) * 4096 + n];
        if (hasX) {
            const float* xr = &g_lstm_in[(b * L_ + t) * 18];
            const float* wr = &Wih[n * 18];
#pragma unroll
            for (int e = 0; e < 18; e++) s = fmaf(xr[e], wr[e], s);
        }
        g[gi] = s;
    }
    float cn = sigm(g[1]) * g_c[idx] + sigm(g[0]) * tanhf(g[2]);
    float hn = sigm(g[3]) * tanhf(cn);
    g_c[idx] = cn;
    g_hbuf[cur ^ 1][idx] = hn;
    if (writeBufRow >= 0) g_buf[(b * M_ + writeBufRow) * H_ + j] = hn;
}

// ---------------- kp init for 127 static rows (one-time) ----------------
__global__ void __launch_bounds__(256) kpinit_k(const float* __restrict__ Wk) {
    int n0 = blockIdx.x * 64, r0 = blockIdx.y * 64;
    __shared__ float sA[16 * 68];
    __shared__ float sW[16 * 68];
    int tid = threadIdx.x, tx = tid & 15, ty = tid >> 4;
    float acc[4][4];
#pragma unroll
    for (int i = 0; i < 4; i++)
#pragma unroll
        for (int j = 0; j < 4; j++) acc[i][j] = 0.0f;
    for (int k0 = 0; k0 < H_; k0 += 16) {
        __syncthreads();
#pragma unroll
        for (int r = 0; r < 4; r++) {
            int e = r * 256 + tid, kk = e & 15, rr = e >> 4;
            int row = r0 + rr, b = row / 127, m = row - b * 127;
            sA[kk * 68 + rr] = g_buf[(b * M_ + m) * H_ + k0 + kk];
        }
#pragma unroll
        for (int r = 0; r < 4; r++) {
            int e = r * 256 + tid, kk = e & 15, nn = e >> 4;
            sW[kk * 68 + nn] = Wk[(n0 + nn) * H_ + k0 + kk];
        }
        __syncthreads();
#pragma unroll
        for (int kk = 0; kk < 16; kk++) {
            float4 av = *(const float4*)&sA[kk * 68 + ty * 4];
            float4 bv = *(const float4*)&sW[kk * 68 + tx * 4];
            float a4[4] = {av.x, av.y, av.z, av.w};
            float b4[4] = {bv.x, bv.y, bv.z, bv.w};
#pragma unroll
            for (int i = 0; i < 4; i++)
#pragma unroll
                for (int j = 0; j < 4; j++) acc[i][j] = fmaf(a4[i], b4[j], acc[i][j]);
        }
    }
#pragma unroll
    for (int i = 0; i < 4; i++) {
        int row = r0 + ty * 4 + i, b = row / 127, m = row - b * 127;
#pragma unroll
        for (int j = 0; j < 4; j++)
            g_kp[(b * M_ + m) * A_ + n0 + tx * 4 + j] = acc[i][j];
    }
}

// ---------------- merged: kp row 127+t (h@Wk^T) + qp ([h;c]@Wq^T) ----------------
__global__ void __launch_bounds__(256) kqp_k(const float* __restrict__ Wk,
                                             const float* __restrict__ Wq,
                                             int cur, int t) {
    int a0 = blockIdx.x * 32, b0 = blockIdx.y * 8;
    const float* __restrict__ h = g_hbuf[cur];
    __shared__ float sWk[32 * 33];
    __shared__ float sWq[32 * 33];
    __shared__ float sH[32 * 8];
    __shared__ float sC[32 * 8];
    int tid = threadIdx.x, lane = tid & 31, wid = tid >> 5;
    float akp = 0.0f, aq0 = 0.0f, aq1 = 0.0f;
    for (int k0 = 0; k0 < H_; k0 += 32) {
        __syncthreads();
#pragma unroll
        for (int r = 0; r < 4; r++) {
            int e = r * 256 + tid, kk = e & 31, a = e >> 5;
            sWk[kk * 33 + a] = Wk[(a0 + a) * H_ + k0 + kk];
            sWq[kk * 33 + a] = Wq[(a0 + a) * H_ + k0 + kk];
        }
        {
            int kk = tid & 31, bb = tid >> 5;
            sH[kk * 8 + bb] = h[(b0 + bb) * H_ + k0 + kk];
            sC[kk * 8 + bb] = g_c[(b0 + bb) * H_ + k0 + kk];
        }
        __syncthreads();
#pragma unroll
        for (int kk = 0; kk < 32; kk++) {
            float hv = sH[kk * 8 + wid], cv = sC[kk * 8 + wid];
            float wk = sWk[kk * 33 + lane], wq = sWq[kk * 33 + lane];
            akp = fmaf(hv, wk, akp);
            aq0 = fmaf(hv, wq, aq0);
            aq1 = fmaf(cv, wq, aq1);
        }
    }
    int b = b0 + wid;
    g_kp[((b * M_) + 127 + t) * A_ + a0 + lane] = akp;
    g_qp[b * 512 + a0 + lane] = aq0;
    g_qp[b * 512 + 256 + a0 + lane] = aq1;
}

// ---------------- scores + 2-way softmax ----------------
__global__ void __launch_bounds__(256) attn_scores_k(const float* __restrict__ Wv, int t) {
    int b = blockIdx.y;
    int m = blockIdx.x * 8 + (threadIdx.x >> 5);
    int lane = threadIdx.x & 31, Mt = 128 + t;
    __shared__ float sqp[512];
    __shared__ float sv[256];
    for (int e = threadIdx.x; e < 512; e += 256) sqp[e] = g_qp[b * 512 + e];
    if (threadIdx.x < 256) sv[threadIdx.x] = Wv[threadIdx.x];
    __syncthreads();
    if (m < Mt) {
        const float* kpm = &g_kp[(b * M_ + m) * A_];
        float s0 = 0.0f, s1 = 0.0f;
#pragma unroll
        for (int aa = 0; aa < 8; aa++) {
            int a = lane + aa * 32;
            float kv = kpm[a], v = sv[a];
            s0 = fmaf(ftanh(sqp[a] + kv), v, s0);
            s1 = fmaf(ftanh(sqp[256 + a] + kv), v, s1);
        }
#pragma unroll
        for (int off = 16; off > 0; off >>= 1) {
            s0 += __shfl_down_sync(0xffffffffu, s0, off);
            s1 += __shfl_down_sync(0xffffffffu, s1, off);
        }
        if (lane == 0) {
            float mx = fmaxf(s0, s1);
            float e0 = __expf(s0 - mx), e1 = __expf(s1 - mx);
            float inv = 1.0f / (e0 + e1);
            g_wts[b * 2 * M_ + m] = e0 * inv;
            g_wts[b * 2 * M_ + M_ + m] = e1 * inv;
        }
    }
}

// ---------------- ctx ----------------
__global__ void __launch_bounds__(256) ctx_k(int t) {
    int b = blockIdx.y;
    int hh = blockIdx.x * 256 + threadIdx.x;
    int Mt = 128 + t;
    __shared__ float w0[M_], w1[M_];
    for (int e = threadIdx.x; e < Mt; e += 256) {
        w0[e] = g_wts[b * 2 * M_ + e];
        w1[e] = g_wts[b * 2 * M_ + M_ + e];
    }
    __syncthreads();
    float a0 = 0.0f, a1 = 0.0f;
    const float* bp = &g_buf[b * M_ * H_ + hh];
    for (int m = 0; m < Mt; m++) {
        float v = bp[m * H_];
        a0 = fmaf(w0[m], v, a0);
        a1 = fmaf(w1[m], v, a1);
    }
    g_ctx[b * 2048 + hh] = a0;
    g_ctx[b * 2048 + 1024 + hh] = a1;
}

// ---------------- output projection ----------------
__global__ void __launch_bounds__(256) out_k(const float* __restrict__ ow,
                                             const float* __restrict__ ob,
                                             int idx, int t, float* __restrict__ out) {
    int b = blockIdx.x;
    const float* h = g_hbuf[idx];
    float s = 0.0f;
    for (int k = threadIdx.x; k < H_; k += 256) s = fmaf(h[b * H_ + k], ow[k], s);
    __shared__ float red[256];
    red[threadIdx.x] = s;
    __syncthreads();
    for (int off = 128; off > 0; off >>= 1) {
        if (threadIdx.x < off) red[threadIdx.x] += red[threadIdx.x + off];
        __syncthreads();
    }
    if (threadIdx.x == 0) out[b * TOUT_ + t] = red[0] + ob[0];
}

extern "C" void kernel_launch(void* const* d_in, const int* in_sizes, int n_in,
                              void* d_out, int out_size) {
    const float* x    = (const float*)d_in[0];
    const float* c1w  = (const float*)d_in[1];
    const float* c1b  = (const float*)d_in[2];
    const float* c2w  = (const float*)d_in[3];
    const float* c2b  = (const float*)d_in[4];
    const float* l3w  = (const float*)d_in[5];
    const float* l3b  = (const float*)d_in[6];
    const float* eWih = (const float*)d_in[7];
    const float* eWhh = (const float*)d_in[8];
    const float* eb   = (const float*)d_in[9];
    const float* Wq   = (const float*)d_in[10];
    const float* Wk   = (const float*)d_in[11];
    const float* Wv   = (const float*)d_in[12];
    const float* dWih = (const float*)d_in[13];
    const float* dWhh = (const float*)d_in[14];
    const float* db   = (const float*)d_in[15];
    const float* ow   = (const float*)d_in[16];
    const float* ob   = (const float*)d_in[17];
    float* out = (float*)d_out;

    zero_k<<<(B_ * H_ + 255) / 256, 256>>>();
    conv_k<36, 34, 48, 0, 0><<<B_, 128>>>(x, c1w, c1b);   // softplus
    conv_k<34, 32, 34, 1, 1><<<B_, 128>>>(x, c2w, c2b);   // relu
    lin3_k<<<B_, 256>>>(x, l3w, l3b);

    int cur = 0;
    for (int t = 0; t < L_; t++) {
        gates_k<<<dim3(32, KS_), 256>>>(0, cur, eWhh, H_, eWhh, H_, H_, H_ / KS_);
        lstm_pw_k<<<512, 256>>>(eWih, eb, t, cur, 1, t);
        cur ^= 1;
    }
    kpinit_k<<<dim3(4, 254), 256>>>(Wk);
    for (int t = 0; t < TOUT_; t++) {
        kqp_k<<<dim3(8, 16), 256>>>(Wk, Wq, cur, t);
        attn_scores_k<<<dim3(19, B_), 256>>>(Wv, t);
        ctx_k<<<dim3(4, B_), 256>>>(t);
        gates_k<<<dim3(32, KS_), 256>>>(1, cur, dWih, 2 * H_, dWhh, H_, 2 * H_, 3 * H_ / KS_);
        lstm_pw_k<<<512, 256>>>(eWih, db, t, cur, 0, (t < 23) ? 128 + t : -1);
        out_k<<<B_, 256>>>(ow, ob, cur ^ 1, t, out);
        cur ^= 1;
    }
}

// round 11
// speedup vs baseline: 1.6135x; 1.0438x over previous
#include <cuda_runtime.h>
#include <math.h>

#define B_ 128
#define L_ 128
#define H_ 1024
#define A_ 256
#define M_ 151
#define TOUT_ 24
#define KS_ 8

typedef unsigned long long u64;

__device__ float g_h1[B_ * L_ * 34];
__device__ float g_h2[B_ * L_ * 32];
__device__ float g_lstm_in[B_ * L_ * 18];
__device__ float g_buf[B_ * M_ * H_];
__device__ float g_hbuf[2][B_ * H_];
__device__ float g_c[B_ * H_];
__device__ float g_kp[B_ * M_ * A_];
__device__ float g_qp[B_ * 2 * A_];
__device__ float g_wts[B_ * 2 * M_];
__device__ float g_ctx[B_ * 2 * H_];
__device__ float g_gpart[KS_ * B_ * 4096];   // split-K partial gates

__device__ __forceinline__ float sigm(float x) { return 1.0f / (1.0f + __expf(-x)); }
__device__ __forceinline__ float ftanh(float x) {
    float e = __expf(-2.0f * fabsf(x));
    float t = (1.0f - e) * __frcp_rn(1.0f + e);
    return copysignf(t, x);
}

// ---- packed fp32x2 FMA (Blackwell FFMA2; ptxas never auto-generates) ----
__device__ __forceinline__ u64 pack2(float lo, float hi) {
    u64 r; asm("mov.b64 %0, {%1, %2};" : "=l"(r) : "f"(lo), "f"(hi)); return r;
}
__device__ __forceinline__ void fma2(u64& d, u64 a, u64 b) {
    asm("fma.rn.f32x2 %0, %1, %2, %0;" : "+l"(d) : "l"(a), "l"(b));
}
__device__ __forceinline__ float2 unpack2(u64 v) {
    float2 f; asm("mov.b64 {%0, %1}, %2;" : "=f"(f.x), "=f"(f.y) : "l"(v)); return f;
}

__global__ void zero_k() {
    int i = blockIdx.x * blockDim.x + threadIdx.x;
    if (i < B_ * H_) { g_hbuf[0][i] = 0.0f; g_c[i] = 0.0f; }
}

// ---------------- conv frontend ----------------
template <int WIN, int WOUT, int ISTRIDE, int ACT, int SRC>
__global__ void __launch_bounds__(128) conv_k(const float* __restrict__ xin,
                                              const float* __restrict__ W,
                                              const float* __restrict__ bias) {
    int b = blockIdx.x, o = threadIdx.x;
    const float* in = (SRC == 0) ? xin : g_h1;
    float* out = (SRC == 0) ? g_h1 : g_h2;
    __shared__ float sIn[16 * WIN];
    float acc[WOUT];
#pragma unroll
    for (int w = 0; w < WOUT; w++) acc[w] = 0.0f;
    for (int i0 = 0; i0 < 128; i0 += 16) {
        __syncthreads();
        for (int e = o; e < 16 * WIN; e += 128) {
            int ii = e / WIN, w = e - ii * WIN;
            sIn[e] = in[(b * 128 + i0 + ii) * ISTRIDE + w];
        }
        __syncthreads();
        float wr[48];
        const float4* wp = reinterpret_cast<const float4*>(&W[(o * 128 + i0) * 3]);
#pragma unroll
        for (int q = 0; q < 12; q++) {
            float4 v = wp[q];
            wr[q * 4] = v.x; wr[q * 4 + 1] = v.y; wr[q * 4 + 2] = v.z; wr[q * 4 + 3] = v.w;
        }
#pragma unroll
        for (int ii = 0; ii < 16; ii++)
#pragma unroll
            for (int w = 0; w < WOUT; w++)
                acc[w] = fmaf(wr[ii * 3], sIn[ii * WIN + w],
                         fmaf(wr[ii * 3 + 1], sIn[ii * WIN + w + 1],
                         fmaf(wr[ii * 3 + 2], sIn[ii * WIN + w + 2], acc[w])));
    }
    float bv = bias[o];
#pragma unroll
    for (int w = 0; w < WOUT; w++) {
        float v = acc[w] + bv;
        if (ACT == 0) v = (v > 20.0f) ? v : log1pf(__expf(v));
        else          v = fmaxf(v, 0.0f);
        out[(b * 128 + o) * WOUT + w] = v;
    }
}

__global__ void __launch_bounds__(256) lin3_k(const float* __restrict__ x,
                                              const float* __restrict__ Wl,
                                              const float* __restrict__ bl) {
    int b = blockIdx.x;
    __shared__ float s2[128 * 32];
    for (int e = threadIdx.x; e < 128 * 32; e += 256) s2[e] = g_h2[b * 128 * 32 + e];
    __syncthreads();
    for (int idx = threadIdx.x; idx < 128 * 18; idx += 256) {
        int l = idx / 18, j = idx - l * 18;
        float v;
        if (j < 6) {
            float a = bl[j];
#pragma unroll
            for (int f = 0; f < 32; f++) a = fmaf(s2[l * 32 + f], Wl[j * 32 + f], a);
            v = a;
        } else v = x[(b * 128 + l) * 48 + 36 + (j - 6)];
        g_lstm_in[(b * 128 + l) * 18 + j] = v;
    }
}

// ---------------- split-K gate GEMM with FFMA2 ----------------
// gpart[ks][b][n] = sum_{k in chunk ks} A[b][k] * W[n][k]
// A(k) = k<len0 ? A0 : A1 ; W(n,k) = k<len0 ? W0 : W1.
// Tile: 128b x 128n, micro 8x8, 256 threads. grid (32 n-tiles, KS_).
__global__ void __launch_bounds__(256, 2) gates_k(
    int asel, int cur,
    const float* __restrict__ W0, int ldw0,
    const float* __restrict__ W1, int ldw1,
    int len0, int kChunk)
{
    const float *A0, *A1;
    int lda0, lda1;
    if (asel == 0) { A0 = g_hbuf[cur]; lda0 = H_; A1 = A0; lda1 = H_; }
    else           { A0 = g_ctx;       lda0 = 2 * H_; A1 = g_hbuf[cur]; lda1 = H_; }

    const int j0 = blockIdx.x * 32;
    const int ks = blockIdx.y;
    const int kbase = ks * kChunk;
    __shared__ float sA[16 * 132];
    __shared__ float sB[16 * 132];
    int tid = threadIdx.x, tx = tid & 15, ty = tid >> 4;

    u64 acc[8][4];
#pragma unroll
    for (int i = 0; i < 8; i++)
#pragma unroll
        for (int jp = 0; jp < 4; jp++) acc[i][jp] = 0ull;

    for (int kb = 0; kb < kChunk; kb += 16) {
        __syncthreads();
#pragma unroll
        for (int r = 0; r < 8; r++) {
            int e = r * 256 + tid;
            int kk = e & 15, bb = e >> 4;
            int kg = kbase + kb + kk;
            float v = (kg < len0) ? A0[bb * lda0 + kg] : A1[bb * lda1 + kg - len0];
            sA[kk * 132 + bb] = v;
        }
#pragma unroll
        for (int r = 0; r < 8; r++) {
            int e = r * 256 + tid;
            int kk = e & 15, n = e >> 4;
            int row = ((n >> 5) << 10) + j0 + (n & 31);
            int kg = kbase + kb + kk;
            float v = (kg < len0) ? W0[row * ldw0 + kg] : W1[row * ldw1 + kg - len0];
            sB[kk * 132 + n] = v;
        }
        __syncthreads();
#pragma unroll
        for (int kk = 0; kk < 16; kk++) {
            float4 b0 = *(const float4*)&sB[kk * 132 + tx * 8];
            float4 b1 = *(const float4*)&sB[kk * 132 + tx * 8 + 4];
            u64 bp[4];
            bp[0] = pack2(b0.x, b0.y); bp[1] = pack2(b0.z, b0.w);
            bp[2] = pack2(b1.x, b1.y); bp[3] = pack2(b1.z, b1.w);
            float4 a0v = *(const float4*)&sA[kk * 132 + ty * 8];
            float4 a1v = *(const float4*)&sA[kk * 132 + ty * 8 + 4];
            float aa[8] = {a0v.x, a0v.y, a0v.z, a0v.w, a1v.x, a1v.y, a1v.z, a1v.w};
#pragma unroll
            for (int i = 0; i < 8; i++) {
                u64 ap = pack2(aa[i], aa[i]);
#pragma unroll
                for (int jp = 0; jp < 4; jp++) fma2(acc[i][jp], ap, bp[jp]);
            }
        }
    }
    // store: 8 consecutive n within one gate-group (tx*8), 8 b rows
    int nl = tx * 8;
    int row = ((nl >> 5) << 10) + j0 + (nl & 31);
#pragma unroll
    for (int i = 0; i < 8; i++) {
        int b = ty * 8 + i;
        float* dst = &g_gpart[((size_t)ks * B_ + b) * 4096 + row];
        float2 p0 = unpack2(acc[i][0]), p1 = unpack2(acc[i][1]);
        float2 p2 = unpack2(acc[i][2]), p3 = unpack2(acc[i][3]);
        float4 v0 = make_float4(p0.x, p0.y, p1.x, p1.y);
        float4 v1 = make_float4(p2.x, p2.y, p3.x, p3.y);
        *(float4*)dst = v0;
        *(float4*)(dst + 4) = v1;
    }
}

// ---------------- reduce partials + (optional input GEMM) + LSTM pointwise ----
__global__ void __launch_bounds__(256) lstm_pw_k(
    const float* __restrict__ Wih,   // [4096][18] (enc only)
    const float* __restrict__ bias,
    int t, int cur, int hasX, int writeBufRow)
{
    int idx = blockIdx.x * 256 + threadIdx.x;   // (b, j)
    int b = idx >> 10, j = idx & 1023;
    float g[4];
#pragma unroll
    for (int gi = 0; gi < 4; gi++) {
        int n = gi * 1024 + j;
        float s = bias[n];
#pragma unroll
        for (int ks = 0; ks < KS_; ks++)
            s += g_gpart[((size_t)ks * B_ + b) * 4096 + n];
        if (hasX) {
            const float* xr = &g_lstm_in[(b * L_ + t) * 18];
            const float* wr = &Wih[n * 18];
#pragma unroll
            for (int e = 0; e < 18; e++) s = fmaf(xr[e], wr[e], s);
        }
        g[gi] = s;
    }
    float cn = sigm(g[1]) * g_c[idx] + sigm(g[0]) * tanhf(g[2]);
    float hn = sigm(g[3]) * tanhf(cn);
    g_c[idx] = cn;
    g_hbuf[cur ^ 1][idx] = hn;
    if (writeBufRow >= 0) g_buf[(b * M_ + writeBufRow) * H_ + j] = hn;
}

// ---------------- kp init for 127 static rows (one-time) ----------------
__global__ void __launch_bounds__(256) kpinit_k(const float* __restrict__ Wk) {
    int n0 = blockIdx.x * 64, r0 = blockIdx.y * 64;
    __shared__ float sA[16 * 68];
    __shared__ float sW[16 * 68];
    int tid = threadIdx.x, tx = tid & 15, ty = tid >> 4;
    float acc[4][4];
#pragma unroll
    for (int i = 0; i < 4; i++)
#pragma unroll
        for (int j = 0; j < 4; j++) acc[i][j] = 0.0f;
    for (int k0 = 0; k0 < H_; k0 += 16) {
        __syncthreads();
#pragma unroll
        for (int r = 0; r < 4; r++) {
            int e = r * 256 + tid, kk = e & 15, rr = e >> 4;
            int row = r0 + rr, b = row / 127, m = row - b * 127;
            sA[kk * 68 + rr] = g_buf[(b * M_ + m) * H_ + k0 + kk];
        }
#pragma unroll
        for (int r = 0; r < 4; r++) {
            int e = r * 256 + tid, kk = e & 15, nn = e >> 4;
            sW[kk * 68 + nn] = Wk[(n0 + nn) * H_ + k0 + kk];
        }
        __syncthreads();
#pragma unroll
        for (int kk = 0; kk < 16; kk++) {
            float4 av = *(const float4*)&sA[kk * 68 + ty * 4];
            float4 bv = *(const float4*)&sW[kk * 68 + tx * 4];
            float a4[4] = {av.x, av.y, av.z, av.w};
            float b4[4] = {bv.x, bv.y, bv.z, bv.w};
#pragma unroll
            for (int i = 0; i < 4; i++)
#pragma unroll
                for (int j = 0; j < 4; j++) acc[i][j] = fmaf(a4[i], b4[j], acc[i][j]);
        }
    }
#pragma unroll
    for (int i = 0; i < 4; i++) {
        int row = r0 + ty * 4 + i, b = row / 127, m = row - b * 127;
#pragma unroll
        for (int j = 0; j < 4; j++)
            g_kp[(b * M_ + m) * A_ + n0 + tx * 4 + j] = acc[i][j];
    }
}

// ---------------- merged: kp row 127+t (h@Wk^T) + qp ([h;c]@Wq^T) ----------------
__global__ void __launch_bounds__(256) kqp_k(const float* __restrict__ Wk,
                                             const float* __restrict__ Wq,
                                             int cur, int t) {
    int a0 = blockIdx.x * 32, b0 = blockIdx.y * 8;
    const float* __restrict__ h = g_hbuf[cur];
    __shared__ float sWk[32 * 33];
    __shared__ float sWq[32 * 33];
    __shared__ float sH[32 * 8];
    __shared__ float sC[32 * 8];
    int tid = threadIdx.x, lane = tid & 31, wid = tid >> 5;
    float akp = 0.0f, aq0 = 0.0f, aq1 = 0.0f;
    for (int k0 = 0; k0 < H_; k0 += 32) {
        __syncthreads();
#pragma unroll
        for (int r = 0; r < 4; r++) {
            int e = r * 256 + tid, kk = e & 31, a = e >> 5;
            sWk[kk * 33 + a] = Wk[(a0 + a) * H_ + k0 + kk];
            sWq[kk * 33 + a] = Wq[(a0 + a) * H_ + k0 + kk];
        }
        {
            int kk = tid & 31, bb = tid >> 5;
            sH[kk * 8 + bb] = h[(b0 + bb) * H_ + k0 + kk];
            sC[kk * 8 + bb] = g_c[(b0 + bb) * H_ + k0 + kk];
        }
        __syncthreads();
#pragma unroll
        for (int kk = 0; kk < 32; kk++) {
            float hv = sH[kk * 8 + wid], cv = sC[kk * 8 + wid];
            float wk = sWk[kk * 33 + lane], wq = sWq[kk * 33 + lane];
            akp = fmaf(hv, wk, akp);
            aq0 = fmaf(hv, wq, aq0);
            aq1 = fmaf(cv, wq, aq1);
        }
    }
    int b = b0 + wid;
    g_kp[((b * M_) + 127 + t) * A_ + a0 + lane] = akp;
    g_qp[b * 512 + a0 + lane] = aq0;
    g_qp[b * 512 + 256 + a0 + lane] = aq1;
}

// ---------------- scores + 2-way softmax ----------------
__global__ void __launch_bounds__(256) attn_scores_k(const float* __restrict__ Wv, int t) {
    int b = blockIdx.y;
    int m = blockIdx.x * 8 + (threadIdx.x >> 5);
    int lane = threadIdx.x & 31, Mt = 128 + t;
    __shared__ float sqp[512];
    __shared__ float sv[256];
    for (int e = threadIdx.x; e < 512; e += 256) sqp[e] = g_qp[b * 512 + e];
    if (threadIdx.x < 256) sv[threadIdx.x] = Wv[threadIdx.x];
    __syncthreads();
    if (m < Mt) {
        const float* kpm = &g_kp[(b * M_ + m) * A_];
        float s0 = 0.0f, s1 = 0.0f;
#pragma unroll
        for (int aa = 0; aa < 8; aa++) {
            int a = lane + aa * 32;
            float kv = kpm[a], v = sv[a];
            s0 = fmaf(ftanh(sqp[a] + kv), v, s0);
            s1 = fmaf(ftanh(sqp[256 + a] + kv), v, s1);
        }
#pragma unroll
        for (int off = 16; off > 0; off >>= 1) {
            s0 += __shfl_down_sync(0xffffffffu, s0, off);
            s1 += __shfl_down_sync(0xffffffffu, s1, off);
        }
        if (lane == 0) {
            float mx = fmaxf(s0, s1);
            float e0 = __expf(s0 - mx), e1 = __expf(s1 - mx);
            float inv = 1.0f / (e0 + e1);
            g_wts[b * 2 * M_ + m] = e0 * inv;
            g_wts[b * 2 * M_ + M_ + m] = e1 * inv;
        }
    }
}

// ---------------- ctx ----------------
__global__ void __launch_bounds__(256) ctx_k(int t) {
    int b = blockIdx.y;
    int hh = blockIdx.x * 256 + threadIdx.x;
    int Mt = 128 + t;
    __shared__ float w0[M_], w1[M_];
    for (int e = threadIdx.x; e < Mt; e += 256) {
        w0[e] = g_wts[b * 2 * M_ + e];
        w1[e] = g_wts[b * 2 * M_ + M_ + e];
    }
    __syncthreads();
    float a0 = 0.0f, a1 = 0.0f;
    const float* bp = &g_buf[b * M_ * H_ + hh];
    for (int m = 0; m < Mt; m++) {
        float v = bp[m * H_];
        a0 = fmaf(w0[m], v, a0);
        a1 = fmaf(w1[m], v, a1);
    }
    g_ctx[b * 2048 + hh] = a0;
    g_ctx[b * 2048 + 1024 + hh] = a1;
}

// ---------------- output projection ----------------
__global__ void __launch_bounds__(256) out_k(const float* __restrict__ ow,
                                             const float* __restrict__ ob,
                                             int idx, int t, float* __restrict__ out) {
    int b = blockIdx.x;
    const float* h = g_hbuf[idx];
    float s = 0.0f;
    for (int k = threadIdx.x; k < H_; k += 256) s = fmaf(h[b * H_ + k], ow[k], s);
    __shared__ float red[256];
    red[threadIdx.x] = s;
    __syncthreads();
    for (int off = 128; off > 0; off >>= 1) {
        if (threadIdx.x < off) red[threadIdx.x] += red[threadIdx.x + off];
        __syncthreads();
    }
    if (threadIdx.x == 0) out[b * TOUT_ + t] = red[0] + ob[0];
}

extern "C" void kernel_launch(void* const* d_in, const int* in_sizes, int n_in,
                              void* d_out, int out_size) {
    const float* x    = (const float*)d_in[0];
    const float* c1w  = (const float*)d_in[1];
    const float* c1b  = (const float*)d_in[2];
    const float* c2w  = (const float*)d_in[3];
    const float* c2b  = (const float*)d_in[4];
    const float* l3w  = (const float*)d_in[5];
    const float* l3b  = (const float*)d_in[6];
    const float* eWih = (const float*)d_in[7];
    const float* eWhh = (const float*)d_in[8];
    const float* eb   = (const float*)d_in[9];
    const float* Wq   = (const float*)d_in[10];
    const float* Wk   = (const float*)d_in[11];
    const float* Wv   = (const float*)d_in[12];
    const float* dWih = (const float*)d_in[13];
    const float* dWhh = (const float*)d_in[14];
    const float* db   = (const float*)d_in[15];
    const float* ow   = (const float*)d_in[16];
    const float* ob   = (const float*)d_in[17];
    float* out = (float*)d_out;

    zero_k<<<(B_ * H_ + 255) / 256, 256>>>();
    conv_k<36, 34, 48, 0, 0><<<B_, 128>>>(x, c1w, c1b);   // softplus
    conv_k<34, 32, 34, 1, 1><<<B_, 128>>>(x, c2w, c2b);   // relu
    lin3_k<<<B_, 256>>>(x, l3w, l3b);

    int cur = 0;
    for (int t = 0; t < L_; t++) {
        gates_k<<<dim3(32, KS_), 256>>>(0, cur, eWhh, H_, eWhh, H_, H_, H_ / KS_);
        lstm_pw_k<<<512, 256>>>(eWih, eb, t, cur, 1, t);
        cur ^= 1;
    }
    kpinit_k<<<dim3(4, 254), 256>>>(Wk);
    for (int t = 0; t < TOUT_; t++) {
        kqp_k<<<dim3(8, 16), 256>>>(Wk, Wq, cur, t);
        attn_scores_k<<<dim3(19, B_), 256>>>(Wv, t);
        ctx_k<<<dim3(4, B_), 256>>>(t);
        gates_k<<<dim3(32, KS_), 256>>>(1, cur, dWih, 2 * H_, dWhh, H_, 2 * H_, 3 * H_ / KS_);
        lstm_pw_k<<<512, 256>>>(eWih, db, t, cur, 0, (t < 23) ? 128 + t : -1);
        out_k<<<B_, 256>>>(ow, ob, cur ^ 1, t, out);
        cur ^= 1;
    }
}

// round 13
// speedup vs baseline: 2.7605x; 1.7109x over previous
#include <cuda_runtime.h>
#include <cuda_bf16.h>
#include <math.h>
#include <stdint.h>

#define B_ 128
#define L_ 128
#define H_ 1024
#define A_ 256
#define M_ 151
#define TOUT_ 24
#define KS_ 8
#define NCE 51
#define NCD 144
#define SMEMSZ 73728

typedef unsigned long long u64;
typedef __nv_bfloat16 bf16;

__device__ float g_h1[B_ * L_ * 34];
__device__ float g_h2[B_ * L_ * 32];
__device__ float g_lstm_in[B_ * L_ * 18];
__device__ float g_buf[B_ * M_ * H_];
__device__ float g_hbuf[2][B_ * H_];
__device__ float g_c[B_ * H_];
__device__ float g_kp[B_ * M_ * A_];
__device__ float g_qp[B_ * 2 * A_];
__device__ float g_wts[B_ * 2 * M_];
__device__ float g_ctx[B_ * 2 * H_];
__device__ float g_gpart[KS_ * B_ * 4096];
__device__ bf16 g_hhi[2][B_ * H_];
__device__ bf16 g_hlo[2][B_ * H_];
__device__ bf16 g_cxhi[B_ * 2 * H_];
__device__ bf16 g_cxlo[B_ * 2 * H_];
__device__ bf16 g_xhi[L_ * B_ * 64];
__device__ bf16 g_xlo[L_ * B_ * 64];
__device__ bf16 g_BEe[(size_t)32 * NCE * 8192];
__device__ bf16 g_BEd[(size_t)32 * NCD * 8192];

__device__ __forceinline__ float sigm(float x) { return 1.0f / (1.0f + __expf(-x)); }
__device__ __forceinline__ float ftanh(float x) {
    float e = __expf(-2.0f * fabsf(x));
    float t = (1.0f - e) * __frcp_rn(1.0f + e);
    return copysignf(t, x);
}
__device__ __forceinline__ bf16 bhi(float v) { return __float2bfloat16_rn(v); }
__device__ __forceinline__ bf16 blo(float v) {
    return __float2bfloat16_rn(v - __bfloat162float(__float2bfloat16_rn(v)));
}
__device__ __forceinline__ uint32_t s2u(const void* p) {
    uint32_t a;
    asm("{ .reg .u64 t; cvta.to.shared.u64 t, %1; cvt.u32.u64 %0, t; }" : "=r"(a) : "l"(p));
    return a;
}
__device__ __forceinline__ void ldsm4(uint32_t& r0, uint32_t& r1, uint32_t& r2, uint32_t& r3, uint32_t a) {
    asm volatile("ldmatrix.sync.aligned.m8n8.x4.shared.b16 {%0,%1,%2,%3},[%4];"
        : "=r"(r0), "=r"(r1), "=r"(r2), "=r"(r3) : "r"(a));
}
__device__ __forceinline__ void mma16816(float* d, uint32_t a0, uint32_t a1, uint32_t a2, uint32_t a3,
                                         uint32_t b0, uint32_t b1) {
    asm volatile("mma.sync.aligned.m16n8k16.row.col.f32.bf16.bf16.f32 "
                 "{%0,%1,%2,%3},{%4,%5,%6,%7},{%8,%9},{%0,%1,%2,%3};"
        : "+f"(d[0]), "+f"(d[1]), "+f"(d[2]), "+f"(d[3])
        : "r"(a0), "r"(a1), "r"(a2), "r"(a3), "r"(b0), "r"(b1));
}
__device__ __forceinline__ void cpa16(uint32_t d, const void* g) {
    asm volatile("cp.async.cg.shared.global [%0], [%1], 16;" :: "r"(d), "l"(g));
}
__device__ __forceinline__ void cpcommit() { asm volatile("cp.async.commit_group;" ::: "memory"); }
template <int N> __device__ __forceinline__ void cpwait() {
    asm volatile("cp.async.wait_group %0;" :: "n"(N) : "memory");
}

__global__ void zero_k() {
    int i = blockIdx.x * blockDim.x + threadIdx.x;
    if (i < B_ * H_) {
        g_hbuf[0][i] = 0.0f; g_c[i] = 0.0f;
        g_hhi[0][i] = __float2bfloat16(0.0f);
        g_hlo[0][i] = __float2bfloat16(0.0f);
    }
}

// ---------------- conv frontend ----------------
template <int WIN, int WOUT, int ISTRIDE, int ACT, int SRC>
__global__ void __launch_bounds__(128) conv_k(const float* __restrict__ xin,
                                              const float* __restrict__ W,
                                              const float* __restrict__ bias) {
    int b = blockIdx.x, o = threadIdx.x;
    const float* in = (SRC == 0) ? xin : g_h1;
    float* out = (SRC == 0) ? g_h1 : g_h2;
    __shared__ float sIn[16 * WIN];
    float acc[WOUT];
#pragma unroll
    for (int w = 0; w < WOUT; w++) acc[w] = 0.0f;
    for (int i0 = 0; i0 < 128; i0 += 16) {
        __syncthreads();
        for (int e = o; e < 16 * WIN; e += 128) {
            int ii = e / WIN, w = e - ii * WIN;
            sIn[e] = in[(b * 128 + i0 + ii) * ISTRIDE + w];
        }
        __syncthreads();
        float wr[48];
        const float4* wp = reinterpret_cast<const float4*>(&W[(o * 128 + i0) * 3]);
#pragma unroll
        for (int q = 0; q < 12; q++) {
            float4 v = wp[q];
            wr[q * 4] = v.x; wr[q * 4 + 1] = v.y; wr[q * 4 + 2] = v.z; wr[q * 4 + 3] = v.w;
        }
#pragma unroll
        for (int ii = 0; ii < 16; ii++)
#pragma unroll
            for (int w = 0; w < WOUT; w++)
                acc[w] = fmaf(wr[ii * 3], sIn[ii * WIN + w],
                         fmaf(wr[ii * 3 + 1], sIn[ii * WIN + w + 1],
                         fmaf(wr[ii * 3 + 2], sIn[ii * WIN + w + 2], acc[w])));
    }
    float bv = bias[o];
#pragma unroll
    for (int w = 0; w < WOUT; w++) {
        float v = acc[w] + bv;
        if (ACT == 0) v = (v > 20.0f) ? v : log1pf(__expf(v));
        else          v = fmaxf(v, 0.0f);
        out[(b * 128 + o) * WOUT + w] = v;
    }
}

__global__ void __launch_bounds__(256) lin3_k(const float* __restrict__ x,
                                              const float* __restrict__ Wl,
                                              const float* __restrict__ bl) {
    int b = blockIdx.x;
    __shared__ float s2[128 * 32];
    for (int e = threadIdx.x; e < 128 * 32; e += 256) s2[e] = g_h2[b * 128 * 32 + e];
    __syncthreads();
    for (int idx = threadIdx.x; idx < 128 * 18; idx += 256) {
        int l = idx / 18, j = idx - l * 18;
        float v;
        if (j < 6) {
            float a = bl[j];
#pragma unroll
            for (int f = 0; f < 32; f++) a = fmaf(s2[l * 32 + f], Wl[j * 32 + f], a);
            v = a;
        } else v = x[(b * 128 + l) * 48 + 36 + (j - 6)];
        g_lstm_in[(b * 128 + l) * 18 + j] = v;
    }
}

__global__ void __launch_bounds__(64) xep_k() {
    int l = blockIdx.x, b = blockIdx.y, e = threadIdx.x;
    float v = (e < 18) ? g_lstm_in[(b * L_ + l) * 18 + e] : 0.0f;
    size_t o = ((size_t)l * B_ + b) * 64 + e;
    g_xhi[o] = bhi(v);
    g_xlo[o] = blo(v);
}

// weight prep: tile-major K-extended bf16. grid (NC, 32), block 128.
__global__ void __launch_bounds__(128) bew_k(int mode,
                                             const float* __restrict__ Wa,
                                             const float* __restrict__ Wb) {
    int ci = blockIdx.x, cta = blockIdx.y, r = threadIdx.x;
    int gate = r >> 5, jl = r & 31;
    int n = (gate << 10) + (cta << 5) + jl;
    int NC = mode ? NCD : NCE;
    bf16* dst = (mode ? g_BEd : g_BEe) + (((size_t)cta * NC + ci) * 128 + r) * 64;
    for (int kk = 0; kk < 64; kk++) {
        int kg = ci * 64 + kk;
        float w; int lo;
        if (mode == 0) {
            if (kg < 3072) { int seg = kg >> 10, k = kg & 1023; w = Wa[n * H_ + k]; lo = (seg == 2); }
            else { int s = kg - 3072, seg = s >> 6, q = s & 63;
                   w = (q < 18) ? Wb[n * 18 + q] : 0.0f; lo = (seg == 2); }
        } else {
            if (kg < 6144) { int seg = kg >> 11, k = kg & 2047; w = Wa[n * 2048 + k]; lo = (seg == 2); }
            else { int s = kg - 6144, seg = s >> 10, k = s & 1023; w = Wb[n * H_ + k]; lo = (seg == 2); }
        }
        dst[kk] = lo ? blo(w) : bhi(w);
    }
}

__device__ __forceinline__ const bf16* asrc(int mode, int ci, int cur, int t, int& stride) {
    if (mode == 0) {
        if (ci < 48) {
            stride = H_;
            if (ci < 16) return g_hhi[cur] + 64 * ci;
            if (ci < 32) return g_hlo[cur] + 64 * (ci - 16);
            return g_hhi[cur] + 64 * (ci - 32);
        }
        stride = 64;
        const bf16* x = (ci == 49) ? g_xlo : g_xhi;
        return x + (size_t)t * B_ * 64;
    }
    if (ci < 96) {
        stride = 2 * H_;
        if (ci < 32) return g_cxhi + 64 * ci;
        if (ci < 64) return g_cxlo + 64 * (ci - 32);
        return g_cxhi + 64 * (ci - 64);
    }
    stride = H_;
    if (ci < 112) return g_hhi[cur] + 64 * (ci - 96);
    if (ci < 128) return g_hlo[cur] + 64 * (ci - 112);
    return g_hhi[cur] + 64 * (ci - 128);
}

// ---------------- split-K bf16 mma.sync gate GEMM ----------------
// grid (32 n-tiles, KS_), 256 threads. Tile M=128(b) x N=128. Chunk = 64 K cols.
// smem: 2 buffers x (A 128x72 + B 128x72) bf16. Row stride 72 bf16 = 144 B.
__global__ void __launch_bounds__(256, 2) mma_k(int mode, int cur, int t) {
    extern __shared__ char sm[];
    uint32_t sb = s2u(sm);
    int tid = threadIdx.x, wid = tid >> 5, lane = tid & 31;
    int cta = blockIdx.x, ks = blockIdx.y;
    int NC = mode ? NCD : NCE;
    int q = NC / KS_, rp = NC % KS_;
    int c0 = ks * q + min(ks, rp);
    int cnt = q + (ks < rp ? 1 : 0);
    const bf16* BE = (mode ? g_BEd : g_BEe) + ((size_t)cta * NC) * 8192;
    int wm = (wid & 3) * 32, wn = (wid >> 2) * 64;

    float acc[2][8][4];
#pragma unroll
    for (int mf = 0; mf < 2; mf++)
#pragma unroll
        for (int nf = 0; nf < 8; nf++)
#pragma unroll
            for (int r = 0; r < 4; r++) acc[mf][nf][r] = 0.0f;

    int lrow = tid >> 3, lj = tid & 7;   // loader: 4 passes of (row, uint4-col)

    // prologue: issue chunk c0 into buffer 0
    {
        int stride;
        const bf16* as = asrc(mode, c0, cur, t, stride);
        const bf16* bs = BE + (size_t)c0 * 8192;
#pragma unroll
        for (int p = 0; p < 4; p++) {
            int row = lrow + p * 32;
            uint32_t da = sb + row * 144 + lj * 16;
            cpa16(da, as + (size_t)row * stride + lj * 8);
            cpa16(da + 18432, bs + row * 64 + lj * 8);
        }
        cpcommit();
    }

    for (int i = 0; i < cnt; i++) {
        if (i + 1 < cnt) {
            int ci = c0 + i + 1, bf = (i + 1) & 1;
            int stride;
            const bf16* as = asrc(mode, ci, cur, t, stride);
            const bf16* bs = BE + (size_t)ci * 8192;
#pragma unroll
            for (int p = 0; p < 4; p++) {
                int row = lrow + p * 32;
                uint32_t da = sb + bf * 36864 + row * 144 + lj * 16;
                cpa16(da, as + (size_t)row * stride + lj * 8);
                cpa16(da + 18432, bs + row * 64 + lj * 8);
            }
            cpcommit();
            cpwait<1>();
        } else {
            cpwait<0>();
        }
        __syncthreads();

        uint32_t base = sb + (i & 1) * 36864;
#pragma unroll
        for (int kst = 0; kst < 4; kst++) {
            uint32_t bfr[8][2];
#pragma unroll
            for (int nf2 = 0; nf2 < 4; nf2++) {
                int rrow = wn + nf2 * 16 + ((lane >> 4) << 3) + (lane & 7);
                uint32_t addr = base + 18432 + rrow * 144 + kst * 32 + ((lane >> 3) & 1) * 16;
                uint32_t r0, r1, r2, r3;
                ldsm4(r0, r1, r2, r3, addr);
                bfr[nf2 * 2][0] = r0; bfr[nf2 * 2][1] = r1;
                bfr[nf2 * 2 + 1][0] = r2; bfr[nf2 * 2 + 1][1] = r3;
            }
#pragma unroll
            for (int mf = 0; mf < 2; mf++) {
                int arow = wm + mf * 16 + (lane & 15);
                uint32_t aaddr = base + arow * 144 + kst * 32 + ((lane >> 4) << 4);
                uint32_t a0, a1, a2, a3;
                ldsm4(a0, a1, a2, a3, aaddr);
#pragma unroll
                for (int nf = 0; nf < 8; nf++)
                    mma16816(acc[mf][nf], a0, a1, a2, a3, bfr[nf][0], bfr[nf][1]);
            }
        }
        __syncthreads();
    }

    size_t gb = (size_t)ks * B_ * 4096;
#pragma unroll
    for (int mf = 0; mf < 2; mf++) {
        int m0 = wm + mf * 16 + (lane >> 2);
#pragma unroll
        for (int nf = 0; nf < 8; nf++) {
            int ntile = wn + nf * 8 + ((lane & 3) << 1);
            int grow = ((ntile >> 5) << 10) + cta * 32 + (ntile & 31);
            *(float2*)&g_gpart[gb + (size_t)m0 * 4096 + grow] =
                make_float2(acc[mf][nf][0], acc[mf][nf][1]);
            *(float2*)&g_gpart[gb + (size_t)(m0 + 8) * 4096 + grow] =
                make_float2(acc[mf][nf][2], acc[mf][nf][3]);
        }
    }
}

// ---------------- reduce partials + LSTM pointwise + bf16 splits ----------------
__global__ void __launch_bounds__(256) lstm_pw_k(const float* __restrict__ bias,
                                                 int cur, int bufrow) {
    int idx = blockIdx.x * 256 + threadIdx.x;
    int b = idx >> 10, j = idx & 1023;
    float g[4];
#pragma unroll
    for (int gi = 0; gi < 4; gi++) {
        int n = gi * 1024 + j;
        float s = bias[n];
#pragma unroll
        for (int ks = 0; ks < KS_; ks++)
            s += g_gpart[((size_t)ks * B_ + b) * 4096 + n];
        g[gi] = s;
    }
    float cn = sigm(g[1]) * g_c[idx] + sigm(g[0]) * tanhf(g[2]);
    float hn = sigm(g[3]) * tanhf(cn);
    g_c[idx] = cn;
    g_hbuf[cur ^ 1][idx] = hn;
    g_hhi[cur ^ 1][idx] = bhi(hn);
    g_hlo[cur ^ 1][idx] = blo(hn);
    if (bufrow >= 0) g_buf[((size_t)b * M_ + bufrow) * H_ + j] = hn;
}

// ---------------- kp init (one-time, fp32) ----------------
__global__ void __launch_bounds__(256) kpinit_k(const float* __restrict__ Wk) {
    int n0 = blockIdx.x * 64, r0 = blockIdx.y * 64;
    __shared__ float sA[16 * 68];
    __shared__ float sW[16 * 68];
    int tid = threadIdx.x, tx = tid & 15, ty = tid >> 4;
    float acc[4][4];
#pragma unroll
    for (int i = 0; i < 4; i++)
#pragma unroll
        for (int j = 0; j < 4; j++) acc[i][j] = 0.0f;
    for (int k0 = 0; k0 < H_; k0 += 16) {
        __syncthreads();
#pragma unroll
        for (int rr2 = 0; rr2 < 4; rr2++) {
            int e = rr2 * 256 + tid, kk = e & 15, rr = e >> 4;
            int row = r0 + rr, b = row / 127, m = row - b * 127;
            sA[kk * 68 + rr] = g_buf[(b * M_ + m) * H_ + k0 + kk];
            sW[kk * 68 + rr] = Wk[(n0 + rr) * H_ + k0 + kk];
        }
        __syncthreads();
#pragma unroll
        for (int kk = 0; kk < 16; kk++) {
            float4 av = *(const float4*)&sA[kk * 68 + ty * 4];
            float4 bv = *(const float4*)&sW[kk * 68 + tx * 4];
            float a4[4] = {av.x, av.y, av.z, av.w};
            float b4[4] = {bv.x, bv.y, bv.z, bv.w};
#pragma unroll
            for (int i = 0; i < 4; i++)
#pragma unroll
                for (int j = 0; j < 4; j++) acc[i][j] = fmaf(a4[i], b4[j], acc[i][j]);
        }
    }
#pragma unroll
    for (int i = 0; i < 4; i++) {
        int row = r0 + ty * 4 + i, b = row / 127, m = row - b * 127;
#pragma unroll
        for (int j = 0; j < 4; j++)
            g_kp[(b * M_ + m) * A_ + n0 + tx * 4 + j] = acc[i][j];
    }
}

__global__ void __launch_bounds__(256) kqp_k(const float* __restrict__ Wk,
                                             const float* __restrict__ Wq,
                                             int cur, int t) {
    int a0 = blockIdx.x * 32, b0 = blockIdx.y * 8;
    const float* __restrict__ h = g_hbuf[cur];
    __shared__ float sWk[32 * 33];
    __shared__ float sWq[32 * 33];
    __shared__ float sH[32 * 8];
    __shared__ float sC[32 * 8];
    int tid = threadIdx.x, lane = tid & 31, wid = tid >> 5;
    float akp = 0.0f, aq0 = 0.0f, aq1 = 0.0f;
    for (int k0 = 0; k0 < H_; k0 += 32) {
        __syncthreads();
#pragma unroll
        for (int rr = 0; rr < 4; rr++) {
            int e = rr * 256 + tid, kk = e & 31, a = e >> 5;
            sWk[kk * 33 + a] = Wk[(a0 + a) * H_ + k0 + kk];
            sWq[kk * 33 + a] = Wq[(a0 + a) * H_ + k0 + kk];
        }
        {
            int kk = tid & 31, bb = tid >> 5;
            sH[kk * 8 + bb] = h[(b0 + bb) * H_ + k0 + kk];
            sC[kk * 8 + bb] = g_c[(b0 + bb) * H_ + k0 + kk];
        }
        __syncthreads();
#pragma unroll
        for (int kk = 0; kk < 32; kk++) {
            float hv = sH[kk * 8 + wid], cv = sC[kk * 8 + wid];
            float wk = sWk[kk * 33 + lane], wq = sWq[kk * 33 + lane];
            akp = fmaf(hv, wk, akp);
            aq0 = fmaf(hv, wq, aq0);
            aq1 = fmaf(cv, wq, aq1);
        }
    }
    int b = b0 + wid;
    g_kp[((b * M_) + 127 + t) * A_ + a0 + lane] = akp;
    g_qp[b * 512 + a0 + lane] = aq0;
    g_qp[b * 512 + 256 + a0 + lane] = aq1;
}

__global__ void __launch_bounds__(256) attn_scores_k(const float* __restrict__ Wv, int t) {
    int b = blockIdx.y;
    int m = blockIdx.x * 8 + (threadIdx.x >> 5);
    int lane = threadIdx.x & 31, Mt = 128 + t;
    __shared__ float sqp[512];
    __shared__ float sv[256];
    for (int e = threadIdx.x; e < 512; e += 256) sqp[e] = g_qp[b * 512 + e];
    if (threadIdx.x < 256) sv[threadIdx.x] = Wv[threadIdx.x];
    __syncthreads();
    if (m < Mt) {
        const float* kpm = &g_kp[(b * M_ + m) * A_];
        float s0 = 0.0f, s1 = 0.0f;
#pragma unroll
        for (int aa = 0; aa < 8; aa++) {
            int a = lane + aa * 32;
            float kv = kpm[a], v = sv[a];
            s0 = fmaf(ftanh(sqp[a] + kv), v, s0);
            s1 = fmaf(ftanh(sqp[256 + a] + kv), v, s1);
        }
#pragma unroll
        for (int off = 16; off > 0; off >>= 1) {
            s0 += __shfl_down_sync(0xffffffffu, s0, off);
            s1 += __shfl_down_sync(0xffffffffu, s1, off);
        }
        if (lane == 0) {
            float mx = fmaxf(s0, s1);
            float e0 = __expf(s0 - mx), e1 = __expf(s1 - mx);
            float inv = 1.0f / (e0 + e1);
            g_wts[b * 2 * M_ + m] = e0 * inv;
            g_wts[b * 2 * M_ + M_ + m] = e1 * inv;
        }
    }
}

__global__ void __launch_bounds__(256) ctx_k(int t) {
    int b = blockIdx.y;
    int hh = blockIdx.x * 256 + threadIdx.x;
    int Mt = 128 + t;
    __shared__ float w0[M_], w1[M_];
    for (int e = threadIdx.x; e < Mt; e += 256) {
        w0[e] = g_wts[b * 2 * M_ + e];
        w1[e] = g_wts[b * 2 * M_ + M_ + e];
    }
    __syncthreads();
    float a0 = 0.0f, a1 = 0.0f;
    const float* bp = &g_buf[b * M_ * H_ + hh];
    for (int m = 0; m < Mt; m++) {
        float v = bp[m * H_];
        a0 = fmaf(w0[m], v, a0);
        a1 = fmaf(w1[m], v, a1);
    }
    int o0 = b * 2048 + hh, o1 = o0 + 1024;
    g_ctx[o0] = a0; g_ctx[o1] = a1;
    g_cxhi[o0] = bhi(a0); g_cxlo[o0] = blo(a0);
    g_cxhi[o1] = bhi(a1); g_cxlo[o1] = blo(a1);
}

__global__ void __launch_bounds__(256) out_k(const float* __restrict__ ow,
                                             const float* __restrict__ ob,
                                             int idx, int t, float* __restrict__ out) {
    int b = blockIdx.x;
    const float* h = g_hbuf[idx];
    float s = 0.0f;
    for (int k = threadIdx.x; k < H_; k += 256) s = fmaf(h[b * H_ + k], ow[k], s);
    __shared__ float red[256];
    red[threadIdx.x] = s;
    __syncthreads();
    for (int off = 128; off > 0; off >>= 1) {
        if (threadIdx.x < off) red[threadIdx.x] += red[threadIdx.x + off];
        __syncthreads();
    }
    if (threadIdx.x == 0) out[b * TOUT_ + t] = red[0] + ob[0];
}

extern "C" void kernel_launch(void* const* d_in, const int* in_sizes, int n_in,
                              void* d_out, int out_size) {
    const float* x    = (const float*)d_in[0];
    const float* c1w  = (const float*)d_in[1];
    const float* c1b  = (const float*)d_in[2];
    const float* c2w  = (const float*)d_in[3];
    const float* c2b  = (const float*)d_in[4];
    const float* l3w  = (const float*)d_in[5];
    const float* l3b  = (const float*)d_in[6];
    const float* eWih = (const float*)d_in[7];
    const float* eWhh = (const float*)d_in[8];
    const float* eb   = (const float*)d_in[9];
    const float* Wq   = (const float*)d_in[10];
    const float* Wk   = (const float*)d_in[11];
    const float* Wv   = (const float*)d_in[12];
    const float* dWih = (const float*)d_in[13];
    const float* dWhh = (const float*)d_in[14];
    const float* db   = (const float*)d_in[15];
    const float* ow   = (const float*)d_in[16];
    const float* ob   = (const float*)d_in[17];
    float* out = (float*)d_out;

    cudaFuncSetAttribute(mma_k, cudaFuncAttributeMaxDynamicSharedMemorySize, SMEMSZ);

    zero_k<<<(B_ * H_ + 255) / 256, 256>>>();
    conv_k<36, 34, 48, 0, 0><<<B_, 128>>>(x, c1w, c1b);
    conv_k<34, 32, 34, 1, 1><<<B_, 128>>>(x, c2w, c2b);
    lin3_k<<<B_, 256>>>(x, l3w, l3b);
    xep_k<<<dim3(L_, B_), 64>>>();
    bew_k<<<dim3(NCE, 32), 128>>>(0, eWhh, eWih);
    bew_k<<<dim3(NCD, 32), 128>>>(1, dWih, dWhh);

    int cur = 0;
    for (int t = 0; t < L_; t++) {
        mma_k<<<dim3(32, KS_), 256, SMEMSZ>>>(0, cur, t);
        lstm_pw_k<<<512, 256>>>(eb, cur, t);
        cur ^= 1;
    }
    kpinit_k<<<dim3(4, 254), 256>>>(Wk);
    for (int t = 0; t < TOUT_; t++) {
        kqp_k<<<dim3(8, 16), 256>>>(Wk, Wq, cur, t);
        attn_scores_k<<<dim3(19, B_), 256>>>(Wv, t);
        ctx_k<<<dim3(4, B_), 256>>>(t);
        mma_k<<<dim3(32, KS_), 256, SMEMSZ>>>(1, cur, t);
        lstm_pw_k<<<512, 256>>>(db, cur, (t < 23) ? 128 + t : -1);
        out_k<<<B_, 256>>>(ow, ob, cur ^ 1, t, out);
        cur ^= 1;
    }
}